// round 3
// baseline (speedup 1.0000x reference)
#include <cuda_runtime.h>
#include <cuda_bf16.h>

// MaxPool2d k=2 s=2 on fp32 NCHW (32, 96, 224, 224) -> (32, 96, 112, 112).
// Pure streaming: each input read once. One thread = one output float4
// (4 output pixels) = two float4 loads from each of 2 input rows.
//
// Dimensions (hardcoded per problem shape):
//   NC = 32*96 = 3072, H = W = 224, OH = OW = 112
//   output float4s per row = 112/4 = 28
//   total threads = 3072 * 112 * 28 = 9,633,792  (= 37632 blocks of 256)

#define NC_    3072
#define W_     224
#define OH_    112
#define OW4_   28            // float4s per output row
#define TOTAL_ (NC_ * OH_ * OW4_)

__global__ __launch_bounds__(256)
void maxpool2x2_kernel(const float4* __restrict__ x, float4* __restrict__ out) {
    unsigned int idx = blockIdx.x * 256u + threadIdx.x;   // == output float4 index
    if (idx >= TOTAL_) return;

    unsigned int ox4 = idx % OW4_;           // which float4 within output row
    unsigned int t   = idx / OW4_;
    unsigned int oy  = t % OH_;
    unsigned int nc  = t / OH_;

    // Input: plane nc, rows 2*oy and 2*oy+1, starting at float column 8*ox4.
    // As float4 indices: plane base = nc * (224*224/4), row stride = 224/4 = 56.
    size_t base = (size_t)nc * (W_ * W_ / 4) + (size_t)(2u * oy) * (W_ / 4) + 2u * ox4;

    float4 a0 = x[base];                 // row 2*oy,   cols [8*ox4 .. +3]
    float4 a1 = x[base + 1];             // row 2*oy,   cols [+4 .. +7]
    float4 b0 = x[base + (W_ / 4)];      // row 2*oy+1, cols [8*ox4 .. +3]
    float4 b1 = x[base + (W_ / 4) + 1];  // row 2*oy+1, cols [+4 .. +7]

    float4 r;
    r.x = fmaxf(fmaxf(a0.x, a0.y), fmaxf(b0.x, b0.y));
    r.y = fmaxf(fmaxf(a0.z, a0.w), fmaxf(b0.z, b0.w));
    r.z = fmaxf(fmaxf(a1.x, a1.y), fmaxf(b1.x, b1.y));
    r.w = fmaxf(fmaxf(a1.z, a1.w), fmaxf(b1.z, b1.w));

    out[idx] = r;
}

extern "C" void kernel_launch(void* const* d_in, const int* in_sizes, int n_in,
                              void* d_out, int out_size) {
    const float4* x = (const float4*)d_in[0];
    float4* out = (float4*)d_out;
    const int threads = 256;
    const int blocks = (TOTAL_ + threads - 1) / threads;   // 37632
    maxpool2x2_kernel<<<blocks, threads>>>(x, out);
}